// round 13
// baseline (speedup 1.0000x reference)
#include <cuda_runtime.h>
#include <cuda_fp16.h>
#include <math.h>
#include <stdint.h>

#define NN    4096
#define KDIM  512
#define ODIM  512
#define NH    4
#define DK    128
#define SLOPE 0.2f

#define NCHUNK     128            // NN / 32
#define TROW       40             // gemm2 fp16 smem row stride (halves)
#define TILE_H     (128 * 32)     // packed gmem tile: 128 d-rows x 32 j halves
#define SROW       80             // k_agg smem tile row stride (halves): 160B
#define WSCALE     0.0625f        // 2^-4, cancels in (p0+p1)/(z0+z1)

#define G2_STAGE_B 30720
#define G2_SMEM    (2 * G2_STAGE_B)

// ---------------- device scratch (no runtime allocation) ----------------
__device__ float  g_Wh[NN * ODIM];                 // 8 MB fp32 [j][c]
__device__ __half g_WhT2[NH * NCHUNK * TILE_H];    // fp16 tiles (j-permuted)
__device__ __half g_Hh[NN * KDIM];
__device__ __half g_Hl[NN * KDIM];
__device__ __half g_WTh[ODIM * KDIM];
__device__ __half g_WTl[ODIM * KDIM];
__device__ float2 g_El2[NH * NN];
__device__ float2 g_Er2[NH * NN];
__device__ unsigned g_Am[NCHUNK * NN];
__device__ float  g_part0[NN * ODIM];
__device__ float  g_part1[NN * ODIM];
__device__ float  g_zp0[NH * NN];
__device__ float  g_zp1[NH * NN];

// ---------------- helpers ----------------
__device__ __forceinline__ void mma_f16(float* c, unsigned a0, unsigned a1,
                                        unsigned a2, unsigned a3,
                                        unsigned b0, unsigned b1) {
    asm("mma.sync.aligned.m16n8k16.row.col.f32.f16.f16.f32 "
        "{%0,%1,%2,%3}, {%4,%5,%6,%7}, {%8,%9}, {%0,%1,%2,%3};"
        : "+f"(c[0]), "+f"(c[1]), "+f"(c[2]), "+f"(c[3])
        : "r"(a0), "r"(a1), "r"(a2), "r"(a3), "r"(b0), "r"(b1));
}
__device__ __forceinline__ unsigned packh2(float lo, float hi) {
    __half2 p = __floats2half2_rn(lo, hi);
    return *(unsigned*)&p;
}
__device__ __forceinline__ void cp16(void* smem_dst, const void* gsrc) {
    unsigned s = (unsigned)__cvta_generic_to_shared(smem_dst);
    asm volatile("cp.async.ca.shared.global [%0], [%1], 16;" :: "r"(s), "l"(gsrc));
}

// ---------------------------------------------------------------------------
// Prep kernel: union grid (round-8 exact).
// ---------------------------------------------------------------------------
__global__ __launch_bounds__(256) void k_prep(const int* __restrict__ A,
                                              const float* __restrict__ H,
                                              const float* __restrict__ W) {
    __shared__ float T[32][33];
    int b = blockIdx.x;
    int tid = threadIdx.x;

    if (b < 512) {
        int warp = tid >> 5, lane = tid & 31;
        int i = b * 8 + warp;
        const int* Arow = A + (size_t)i * NN;
        int dc = i >> 5;
        unsigned dbit = 1u << (i & 31);
        for (int c = 0; c < NCHUNK; c++) {
            int v = Arow[c * 32 + lane];
            unsigned bal = __ballot_sync(0xffffffffu, v > 0);
            if (c == dc) bal |= dbit;
            if (lane == 0) g_Am[(size_t)c * NN + i] = bal;
        }
    } else if (b < 2560) {
        int i4 = (b - 512) * 256 + tid;
        float4 v = ((const float4*)H)[i4];
        __half hx = __float2half_rn(v.x), hy = __float2half_rn(v.y);
        __half hz = __float2half_rn(v.z), hw = __float2half_rn(v.w);
        __half2* ph = (__half2*)g_Hh;
        __half2* pl = (__half2*)g_Hl;
        ph[i4 * 2 + 0] = __halves2half2(hx, hy);
        ph[i4 * 2 + 1] = __halves2half2(hz, hw);
        pl[i4 * 2 + 0] = __floats2half2_rn(v.x - __half2float(hx), v.y - __half2float(hy));
        pl[i4 * 2 + 1] = __floats2half2_rn(v.z - __half2float(hz), v.w - __half2float(hw));
    } else {
        int idx = b - 2560;
        int kb = (idx & 15) * 32, nb = (idx >> 4) * 32;
        int x = tid & 31, y = tid >> 5;
#pragma unroll
        for (int q = 0; q < 32; q += 8)
            T[y + q][x] = W[(size_t)(kb + y + q) * ODIM + nb + x];
        __syncthreads();
#pragma unroll
        for (int q = 0; q < 32; q += 8) {
            float v = T[x][y + q];
            __half hi = __float2half_rn(v);
            size_t o = (size_t)(nb + y + q) * KDIM + kb + x;
            g_WTh[o] = hi;
            g_WTl[o] = __float2half_rn(v - __half2float(hi));
        }
    }
}

// ---------------------------------------------------------------------------
// Kernel 1: Wh = H @ W via split-fp16 MMA, 2-stage cp.async (round-8 exact).
// ---------------------------------------------------------------------------
__global__ __launch_bounds__(256) void k_gemm2() {
    extern __shared__ __align__(16) char dsm[];

    int tid = threadIdx.x;
    int warp = tid >> 5, lane = tid & 31;
    int g = lane >> 2, tg = lane & 3;
    int wm = warp & 3, wn = warp >> 2;
    int m0 = blockIdx.y * 128, n0 = blockIdx.x * 64;

    auto issue = [&](int ks, int s) {
        char* base = dsm + s * G2_STAGE_B;
        __half* Ah_ = (__half*)base;
        __half* Al_ = (__half*)(base + 10240);
        __half* Bh_ = (__half*)(base + 20480);
        __half* Bl_ = (__half*)(base + 25600);
        int k0 = ks * 32;
#pragma unroll
        for (int q = 0; q < 2; q++) {
            int f = tid + 256 * q;
            int r = f >> 2, seg = (f & 3) * 8;
            cp16(&Ah_[r * TROW + seg], &g_Hh[(size_t)(m0 + r) * KDIM + k0 + seg]);
            cp16(&Al_[r * TROW + seg], &g_Hl[(size_t)(m0 + r) * KDIM + k0 + seg]);
        }
        {
            int r = tid >> 2, seg = (tid & 3) * 8;
            cp16(&Bh_[r * TROW + seg], &g_WTh[(size_t)(n0 + r) * KDIM + k0 + seg]);
            cp16(&Bl_[r * TROW + seg], &g_WTl[(size_t)(n0 + r) * KDIM + k0 + seg]);
        }
        asm volatile("cp.async.commit_group;");
    };

    float acc[2][4][4];
#pragma unroll
    for (int mt = 0; mt < 2; mt++)
#pragma unroll
        for (int nt = 0; nt < 4; nt++)
#pragma unroll
            for (int q = 0; q < 4; q++) acc[mt][nt][q] = 0.f;

    issue(0, 0);

    for (int ks = 0; ks < KDIM / 32; ks++) {
        int s = ks & 1;
        if (ks + 1 < KDIM / 32) {
            issue(ks + 1, s ^ 1);
            asm volatile("cp.async.wait_group 1;");
        } else {
            asm volatile("cp.async.wait_group 0;");
        }
        __syncthreads();

        const char* base = dsm + s * G2_STAGE_B;
        const __half* Ah_ = (const __half*)base;
        const __half* Al_ = (const __half*)(base + 10240);
        const __half* Bh_ = (const __half*)(base + 20480);
        const __half* Bl_ = (const __half*)(base + 25600);

#pragma unroll
        for (int kt = 0; kt < 2; kt++) {
            int kb = 16 * kt + 2 * tg;
            unsigned ah[2][4], al_[2][4];
#pragma unroll
            for (int mt = 0; mt < 2; mt++) {
                int rb = 32 * wm + 16 * mt + g;
                ah[mt][0] = *(const unsigned*)&Ah_[rb * TROW + kb];
                ah[mt][1] = *(const unsigned*)&Ah_[(rb + 8) * TROW + kb];
                ah[mt][2] = *(const unsigned*)&Ah_[rb * TROW + kb + 8];
                ah[mt][3] = *(const unsigned*)&Ah_[(rb + 8) * TROW + kb + 8];
                al_[mt][0] = *(const unsigned*)&Al_[rb * TROW + kb];
                al_[mt][1] = *(const unsigned*)&Al_[(rb + 8) * TROW + kb];
                al_[mt][2] = *(const unsigned*)&Al_[rb * TROW + kb + 8];
                al_[mt][3] = *(const unsigned*)&Al_[(rb + 8) * TROW + kb + 8];
            }
#pragma unroll
            for (int nt = 0; nt < 4; nt++) {
                int nl = 32 * wn + 8 * nt + g;
                unsigned bh0 = *(const unsigned*)&Bh_[nl * TROW + kb];
                unsigned bh1 = *(const unsigned*)&Bh_[nl * TROW + kb + 8];
                unsigned bl0 = *(const unsigned*)&Bl_[nl * TROW + kb];
                unsigned bl1 = *(const unsigned*)&Bl_[nl * TROW + kb + 8];
#pragma unroll
                for (int mt = 0; mt < 2; mt++) {
                    mma_f16(acc[mt][nt], ah[mt][0], ah[mt][1], ah[mt][2], ah[mt][3], bh0, bh1);
                    mma_f16(acc[mt][nt], ah[mt][0], ah[mt][1], ah[mt][2], ah[mt][3], bl0, bl1);
                    mma_f16(acc[mt][nt], al_[mt][0], al_[mt][1], al_[mt][2], al_[mt][3], bh0, bh1);
                }
            }
        }
        __syncthreads();
    }

#pragma unroll
    for (int mt = 0; mt < 2; mt++)
#pragma unroll
        for (int nt = 0; nt < 4; nt++) {
            int row = m0 + 32 * wm + 16 * mt + g;
            int col = n0 + 32 * wn + 8 * nt + 2 * tg;
            *(float2*)&g_Wh[(size_t)row * ODIM + col] =
                make_float2(acc[mt][nt][0], acc[mt][nt][1]);
            *(float2*)&g_Wh[(size_t)(row + 8) * ODIM + col] =
                make_float2(acc[mt][nt][2], acc[mt][nt][3]);
        }
}

// ---------------------------------------------------------------------------
// Kernel 1b+2: packed j-permuted fp16 tiles + sl/sr tables (round-8 exact).
// ---------------------------------------------------------------------------
__global__ __launch_bounds__(256) void k_whT2s(const float* __restrict__ al,
                                               const float* __restrict__ ar) {
    __shared__ float T[128][33];
    int jc = blockIdx.x, h = blockIdx.y;
    int tid = threadIdx.x;
    int warp = tid >> 5, lane = tid & 31;
    int j0 = jc * 32;

#pragma unroll
    for (int q = 0; q < 4; q++) {
        int f = tid + 256 * q;
        int j = f >> 5;
        int dq = (f & 31) * 4;
        float4 v = *(const float4*)(g_Wh + (size_t)(j0 + j) * ODIM + h * DK + dq);
        T[dq + 0][j] = v.x;
        T[dq + 1][j] = v.y;
        T[dq + 2][j] = v.z;
        T[dq + 3][j] = v.w;
    }
    __syncthreads();

    __half* tile = g_WhT2 + (size_t)(h * NCHUNK + jc) * TILE_H;
#pragma unroll
    for (int q = 0; q < 8; q++) {
        int f = tid + 256 * q;
        int row = f >> 4;
        int jp = f & 15;
        int blk = jp >> 3;
        int qq = jp & 7;
        int slot = ((qq & 3) * 2 + (qq >> 2));
        __half2 hv = __floats2half2_rn(T[row][2 * jp], T[row][2 * jp + 1]);
        *(__half2*)&tile[row * 32 + blk * 16 + slot * 2] = hv;
    }

#pragma unroll
    for (int rr = 0; rr < 4; rr++) {
        int j = warp * 4 + rr;
        float s1 = 0.f, s2 = 0.f;
#pragma unroll
        for (int q = 0; q < 4; q++) {
            int d = lane + 32 * q;
            float v = T[d][j];
            s1 = fmaf(v, al[h * DK + d], s1);
            s2 = fmaf(v, ar[h * DK + d], s2);
        }
#pragma unroll
        for (int o = 16; o > 0; o >>= 1) {
            s1 += __shfl_down_sync(0xffffffffu, s1, o);
            s2 += __shfl_down_sync(0xffffffffu, s2, o);
        }
        if (lane == 0) {
            int i = j0 + j;
            g_El2[h * NN + i] = make_float2(__expf(s1), __expf(SLOPE * s1));
            g_Er2[h * NN + i] = make_float2(__expf(s2), __expf(SLOPE * s2));
        }
    }
}

// ---------------------------------------------------------------------------
// Kernel 3: split-K aggregation. ONLY change vs round 11: CTA additionally
// split over d-halves (z: dhalf = z&1, khalf = z>>1; grid 32x4x4 = 512).
// Warp tile 16i x 64d -> acc 32 floats -> 3 CTAs/SM (24 warps, was 16).
// Per-chunk structure identical (single barrier, alpha once, LDS.64 B).
// ---------------------------------------------------------------------------
__global__ __launch_bounds__(256, 3) void k_agg_p() {
    __shared__ __half Whs[2][64 * SROW];
    __shared__ float4 Ers4[2][16];
    __shared__ unsigned Ams[2][128];

    int tid = threadIdx.x;
    int warp = tid >> 5, lane = tid & 31;
    int g = lane >> 2, tg = lane & 3;
    int h = blockIdx.y;
    int i0 = blockIdx.x * 128;
    int dhalf = blockIdx.z & 1;
    int khalf = blockIdx.z >> 1;
    int cb = khalf * (NCHUNK / 2);

    float el1[2], el2[2];
#pragma unroll
    for (int s = 0; s < 2; s++) {
        int r = i0 + 16 * warp + 8 * s + g;
        float2 e = g_El2[(size_t)h * NN + r];
        el1[s] = e.x * WSCALE;
        el2[s] = e.y * WSCALE;
    }

    auto issue = [&](int cc, int s) {
        // this CTA needs only d-rows [dhalf*64, dhalf*64+64)
        const __half* tp = g_WhT2 + (size_t)(h * NCHUNK + cc) * TILE_H + dhalf * 64 * 32;
        {
            int row = tid >> 2, seg = (tid & 3) * 8;   // 64 rows x 4 segs = 256
            cp16(&Whs[s][row * SROW + seg], tp + row * 32 + seg);
        }
        if (tid < 16) cp16(&Ers4[s][tid], g_Er2 + (size_t)h * NN + cc * 32 + 2 * tid);
        if (tid < 32) cp16(&Ams[s][tid * 4], g_Am + (size_t)cc * NN + i0 + tid * 4);
        asm volatile("cp.async.commit_group;");
    };

    float acc[8][4];
#pragma unroll
    for (int nt = 0; nt < 8; nt++)
#pragma unroll
        for (int q = 0; q < 4; q++) acc[nt][q] = 0.f;
    float zac[2] = {0.f, 0.f};

    issue(cb, 0);

    for (int c = 0; c < NCHUNK / 2; c++) {
        int s = c & 1;
        asm volatile("cp.async.wait_group 0;");
        __syncthreads();
        if (c + 1 < NCHUNK / 2) issue(cb + c + 1, s ^ 1);

        unsigned mw0 = Ams[s][16 * warp + g];
        unsigned mw1 = Ams[s][16 * warp + 8 + g];

        unsigned aF[2][4];
#pragma unroll
        for (int kt = 0; kt < 2; kt++) {
            float4 eA = Ers4[s][8 * kt + tg];
            float4 eB = Ers4[s][8 * kt + tg + 4];
            int jb = 16 * kt + 2 * tg;
            {
                float w0 = fmaxf(el1[0] * eA.x, el2[0] * eA.y);
                if (!((mw0 >> jb) & 1u)) w0 = 0.f;
                float w1 = fmaxf(el1[0] * eA.z, el2[0] * eA.w);
                if (!((mw0 >> (jb + 1)) & 1u)) w1 = 0.f;
                float w8 = fmaxf(el1[0] * eB.x, el2[0] * eB.y);
                if (!((mw0 >> (jb + 8)) & 1u)) w8 = 0.f;
                float w9 = fmaxf(el1[0] * eB.z, el2[0] * eB.w);
                if (!((mw0 >> (jb + 9)) & 1u)) w9 = 0.f;
                zac[0] += (w0 + w1) + (w8 + w9);
                aF[kt][0] = packh2(w0, w1);
                aF[kt][2] = packh2(w8, w9);
            }
            {
                float w0 = fmaxf(el1[1] * eA.x, el2[1] * eA.y);
                if (!((mw1 >> jb) & 1u)) w0 = 0.f;
                float w1 = fmaxf(el1[1] * eA.z, el2[1] * eA.w);
                if (!((mw1 >> (jb + 1)) & 1u)) w1 = 0.f;
                float w8 = fmaxf(el1[1] * eB.x, el2[1] * eB.y);
                if (!((mw1 >> (jb + 8)) & 1u)) w8 = 0.f;
                float w9 = fmaxf(el1[1] * eB.z, el2[1] * eB.w);
                if (!((mw1 >> (jb + 9)) & 1u)) w9 = 0.f;
                zac[1] += (w0 + w1) + (w8 + w9);
                aF[kt][1] = packh2(w0, w1);
                aF[kt][3] = packh2(w8, w9);
            }
        }

#pragma unroll
        for (int kt = 0; kt < 2; kt++) {
#pragma unroll
            for (int nt = 0; nt < 8; nt++) {
                int drow = 8 * nt + g;
                uint2 bb = *(const uint2*)&Whs[s][drow * SROW + 16 * kt + 4 * tg];
                mma_f16(acc[nt], aF[kt][0], aF[kt][1], aF[kt][2], aF[kt][3], bb.x, bb.y);
            }
        }
    }

    // partial Z per row (quad-reduce); identical in both dhalf CTAs -> write once
    if (dhalf == 0) {
        float z0 = zac[0], z1 = zac[1];
        z0 += __shfl_xor_sync(0xffffffffu, z0, 1);
        z0 += __shfl_xor_sync(0xffffffffu, z0, 2);
        z1 += __shfl_xor_sync(0xffffffffu, z1, 1);
        z1 += __shfl_xor_sync(0xffffffffu, z1, 2);
        float* zp = khalf ? g_zp1 : g_zp0;
        if (tg == 0) {
            zp[(size_t)h * NN + i0 + 16 * warp + g] = z0;
            zp[(size_t)h * NN + i0 + 16 * warp + 8 + g] = z1;
        }
    }

    // partial sums to gmem (raw, scaled); this CTA's 64-col d-slice
    float* pp = khalf ? g_part1 : g_part0;
#pragma unroll
    for (int nt = 0; nt < 8; nt++) {
        int col = h * DK + dhalf * 64 + 8 * nt + 2 * tg;
        int row0 = i0 + 16 * warp + g;
        *(float2*)(pp + (size_t)row0 * ODIM + col) = make_float2(acc[nt][0], acc[nt][1]);
        *(float2*)(pp + (size_t)(row0 + 8) * ODIM + col) = make_float2(acc[nt][2], acc[nt][3]);
    }
}

// ---------------------------------------------------------------------------
// Kernel 4: combine halves, normalize, ELU (round-11 exact).
// ---------------------------------------------------------------------------
__global__ __launch_bounds__(256) void k_comb(float* __restrict__ out) {
    int t = blockIdx.x * 256 + threadIdx.x;
    int row = t >> 7;
    int col4 = t & 127;
    int h = col4 >> 5;
    float z = g_zp0[(size_t)h * NN + row] + g_zp1[(size_t)h * NN + row];
    float invz = __fdividef(1.f, z);
    float4 p0 = ((const float4*)g_part0)[t];
    float4 p1 = ((const float4*)g_part1)[t];
    float4 v;
    v.x = (p0.x + p1.x) * invz;
    v.y = (p0.y + p1.y) * invz;
    v.z = (p0.z + p1.z) * invz;
    v.w = (p0.w + p1.w) * invz;
    v.x = v.x > 0.f ? v.x : (__expf(v.x) - 1.f);
    v.y = v.y > 0.f ? v.y : (__expf(v.y) - 1.f);
    v.z = v.z > 0.f ? v.z : (__expf(v.z) - 1.f);
    v.w = v.w > 0.f ? v.w : (__expf(v.w) - 1.f);
    ((float4*)out)[t] = v;
}

// ---------------------------------------------------------------------------
extern "C" void kernel_launch(void* const* d_in, const int* in_sizes, int n_in,
                              void* d_out, int out_size) {
    const float* H  = (const float*)d_in[0];
    const int*   A  = (const int*)d_in[1];
    const float* W  = (const float*)d_in[2];
    const float* al = (const float*)d_in[3];
    const float* ar = (const float*)d_in[4];
    float* out = (float*)d_out;

    cudaFuncSetAttribute(k_gemm2, cudaFuncAttributeMaxDynamicSharedMemorySize,
                         G2_SMEM);

    k_prep<<<2816, 256>>>(A, H, W);
    k_gemm2<<<dim3(ODIM / 64, NN / 128), 256, G2_SMEM>>>();
    k_whT2s<<<dim3(NCHUNK, NH), 256>>>(al, ar);
    k_agg_p<<<dim3(NN / 128, NH, 4), 256>>>();
    k_comb<<<(NN * ODIM / 4) / 256, 256>>>(out);
}

// round 14
// speedup vs baseline: 1.1624x; 1.1624x over previous
#include <cuda_runtime.h>
#include <cuda_fp16.h>
#include <math.h>
#include <stdint.h>

#define NN    4096
#define KDIM  512
#define ODIM  512
#define NH    4
#define DK    128
#define SLOPE 0.2f

#define NCHUNK     128            // NN / 32
#define TROW       40             // gemm2 fp16 smem row stride (halves)
#define TILE_H     (128 * 32)     // packed gmem tile: 128 d-rows x 32 j halves
#define SROW       80             // k_agg smem tile row stride (halves): 160B
#define WSCALE     0.0625f        // 2^-4, cancels in (p0+p1)/(z0+z1)

#define G2_STAGE_B 30720
#define G2_SMEM    (2 * G2_STAGE_B)

// k_agg 3-stage dynamic smem: tile(20480) + Ers(256) + Ams(512) per stage
#define AG_TILE_B  20480
#define AG_ERS_OFF 20480
#define AG_AMS_OFF 20736
#define AG_STAGE_B 21248
#define AG_SMEM    (3 * AG_STAGE_B)   // 63744 B per CTA

// ---------------- device scratch (no runtime allocation) ----------------
__device__ float  g_Wh[NN * ODIM];                 // 8 MB fp32 [j][c]
__device__ __half g_WhT2[NH * NCHUNK * TILE_H];    // fp16 tiles (j-permuted)
__device__ __half g_Hh[NN * KDIM];
__device__ __half g_Hl[NN * KDIM];
__device__ __half g_WTh[ODIM * KDIM];
__device__ __half g_WTl[ODIM * KDIM];
__device__ float2 g_El2[NH * NN];
__device__ float2 g_Er2[NH * NN];
__device__ unsigned g_Am[NCHUNK * NN];
__device__ float  g_part0[NN * ODIM];
__device__ float  g_part1[NN * ODIM];
__device__ float  g_zp0[NH * NN];
__device__ float  g_zp1[NH * NN];

// ---------------- helpers ----------------
__device__ __forceinline__ void mma_f16(float* c, unsigned a0, unsigned a1,
                                        unsigned a2, unsigned a3,
                                        unsigned b0, unsigned b1) {
    asm("mma.sync.aligned.m16n8k16.row.col.f32.f16.f16.f32 "
        "{%0,%1,%2,%3}, {%4,%5,%6,%7}, {%8,%9}, {%0,%1,%2,%3};"
        : "+f"(c[0]), "+f"(c[1]), "+f"(c[2]), "+f"(c[3])
        : "r"(a0), "r"(a1), "r"(a2), "r"(a3), "r"(b0), "r"(b1));
}
__device__ __forceinline__ unsigned packh2(float lo, float hi) {
    __half2 p = __floats2half2_rn(lo, hi);
    return *(unsigned*)&p;
}
__device__ __forceinline__ void cp16(void* smem_dst, const void* gsrc) {
    unsigned s = (unsigned)__cvta_generic_to_shared(smem_dst);
    asm volatile("cp.async.ca.shared.global [%0], [%1], 16;" :: "r"(s), "l"(gsrc));
}

// ---------------------------------------------------------------------------
// Prep kernel: union grid (round-8 exact).
// ---------------------------------------------------------------------------
__global__ __launch_bounds__(256) void k_prep(const int* __restrict__ A,
                                              const float* __restrict__ H,
                                              const float* __restrict__ W) {
    __shared__ float T[32][33];
    int b = blockIdx.x;
    int tid = threadIdx.x;

    if (b < 512) {
        int warp = tid >> 5, lane = tid & 31;
        int i = b * 8 + warp;
        const int* Arow = A + (size_t)i * NN;
        int dc = i >> 5;
        unsigned dbit = 1u << (i & 31);
        for (int c = 0; c < NCHUNK; c++) {
            int v = Arow[c * 32 + lane];
            unsigned bal = __ballot_sync(0xffffffffu, v > 0);
            if (c == dc) bal |= dbit;
            if (lane == 0) g_Am[(size_t)c * NN + i] = bal;
        }
    } else if (b < 2560) {
        int i4 = (b - 512) * 256 + tid;
        float4 v = ((const float4*)H)[i4];
        __half hx = __float2half_rn(v.x), hy = __float2half_rn(v.y);
        __half hz = __float2half_rn(v.z), hw = __float2half_rn(v.w);
        __half2* ph = (__half2*)g_Hh;
        __half2* pl = (__half2*)g_Hl;
        ph[i4 * 2 + 0] = __halves2half2(hx, hy);
        ph[i4 * 2 + 1] = __halves2half2(hz, hw);
        pl[i4 * 2 + 0] = __floats2half2_rn(v.x - __half2float(hx), v.y - __half2float(hy));
        pl[i4 * 2 + 1] = __floats2half2_rn(v.z - __half2float(hz), v.w - __half2float(hw));
    } else {
        int idx = b - 2560;
        int kb = (idx & 15) * 32, nb = (idx >> 4) * 32;
        int x = tid & 31, y = tid >> 5;
#pragma unroll
        for (int q = 0; q < 32; q += 8)
            T[y + q][x] = W[(size_t)(kb + y + q) * ODIM + nb + x];
        __syncthreads();
#pragma unroll
        for (int q = 0; q < 32; q += 8) {
            float v = T[x][y + q];
            __half hi = __float2half_rn(v);
            size_t o = (size_t)(nb + y + q) * KDIM + kb + x;
            g_WTh[o] = hi;
            g_WTl[o] = __float2half_rn(v - __half2float(hi));
        }
    }
}

// ---------------------------------------------------------------------------
// Kernel 1: Wh = H @ W via split-fp16 MMA, 2-stage cp.async (round-8 exact).
// ---------------------------------------------------------------------------
__global__ __launch_bounds__(256) void k_gemm2() {
    extern __shared__ __align__(16) char dsm[];

    int tid = threadIdx.x;
    int warp = tid >> 5, lane = tid & 31;
    int g = lane >> 2, tg = lane & 3;
    int wm = warp & 3, wn = warp >> 2;
    int m0 = blockIdx.y * 128, n0 = blockIdx.x * 64;

    auto issue = [&](int ks, int s) {
        char* base = dsm + s * G2_STAGE_B;
        __half* Ah_ = (__half*)base;
        __half* Al_ = (__half*)(base + 10240);
        __half* Bh_ = (__half*)(base + 20480);
        __half* Bl_ = (__half*)(base + 25600);
        int k0 = ks * 32;
#pragma unroll
        for (int q = 0; q < 2; q++) {
            int f = tid + 256 * q;
            int r = f >> 2, seg = (f & 3) * 8;
            cp16(&Ah_[r * TROW + seg], &g_Hh[(size_t)(m0 + r) * KDIM + k0 + seg]);
            cp16(&Al_[r * TROW + seg], &g_Hl[(size_t)(m0 + r) * KDIM + k0 + seg]);
        }
        {
            int r = tid >> 2, seg = (tid & 3) * 8;
            cp16(&Bh_[r * TROW + seg], &g_WTh[(size_t)(n0 + r) * KDIM + k0 + seg]);
            cp16(&Bl_[r * TROW + seg], &g_WTl[(size_t)(n0 + r) * KDIM + k0 + seg]);
        }
        asm volatile("cp.async.commit_group;");
    };

    float acc[2][4][4];
#pragma unroll
    for (int mt = 0; mt < 2; mt++)
#pragma unroll
        for (int nt = 0; nt < 4; nt++)
#pragma unroll
            for (int q = 0; q < 4; q++) acc[mt][nt][q] = 0.f;

    issue(0, 0);

    for (int ks = 0; ks < KDIM / 32; ks++) {
        int s = ks & 1;
        if (ks + 1 < KDIM / 32) {
            issue(ks + 1, s ^ 1);
            asm volatile("cp.async.wait_group 1;");
        } else {
            asm volatile("cp.async.wait_group 0;");
        }
        __syncthreads();

        const char* base = dsm + s * G2_STAGE_B;
        const __half* Ah_ = (const __half*)base;
        const __half* Al_ = (const __half*)(base + 10240);
        const __half* Bh_ = (const __half*)(base + 20480);
        const __half* Bl_ = (const __half*)(base + 25600);

#pragma unroll
        for (int kt = 0; kt < 2; kt++) {
            int kb = 16 * kt + 2 * tg;
            unsigned ah[2][4], al_[2][4];
#pragma unroll
            for (int mt = 0; mt < 2; mt++) {
                int rb = 32 * wm + 16 * mt + g;
                ah[mt][0] = *(const unsigned*)&Ah_[rb * TROW + kb];
                ah[mt][1] = *(const unsigned*)&Ah_[(rb + 8) * TROW + kb];
                ah[mt][2] = *(const unsigned*)&Ah_[rb * TROW + kb + 8];
                ah[mt][3] = *(const unsigned*)&Ah_[(rb + 8) * TROW + kb + 8];
                al_[mt][0] = *(const unsigned*)&Al_[rb * TROW + kb];
                al_[mt][1] = *(const unsigned*)&Al_[(rb + 8) * TROW + kb];
                al_[mt][2] = *(const unsigned*)&Al_[rb * TROW + kb + 8];
                al_[mt][3] = *(const unsigned*)&Al_[(rb + 8) * TROW + kb + 8];
            }
#pragma unroll
            for (int nt = 0; nt < 4; nt++) {
                int nl = 32 * wn + 8 * nt + g;
                unsigned bh0 = *(const unsigned*)&Bh_[nl * TROW + kb];
                unsigned bh1 = *(const unsigned*)&Bh_[nl * TROW + kb + 8];
                unsigned bl0 = *(const unsigned*)&Bl_[nl * TROW + kb];
                unsigned bl1 = *(const unsigned*)&Bl_[nl * TROW + kb + 8];
#pragma unroll
                for (int mt = 0; mt < 2; mt++) {
                    mma_f16(acc[mt][nt], ah[mt][0], ah[mt][1], ah[mt][2], ah[mt][3], bh0, bh1);
                    mma_f16(acc[mt][nt], ah[mt][0], ah[mt][1], ah[mt][2], ah[mt][3], bl0, bl1);
                    mma_f16(acc[mt][nt], al_[mt][0], al_[mt][1], al_[mt][2], al_[mt][3], bh0, bh1);
                }
            }
        }
        __syncthreads();
    }

#pragma unroll
    for (int mt = 0; mt < 2; mt++)
#pragma unroll
        for (int nt = 0; nt < 4; nt++) {
            int row = m0 + 32 * wm + 16 * mt + g;
            int col = n0 + 32 * wn + 8 * nt + 2 * tg;
            *(float2*)&g_Wh[(size_t)row * ODIM + col] =
                make_float2(acc[mt][nt][0], acc[mt][nt][1]);
            *(float2*)&g_Wh[(size_t)(row + 8) * ODIM + col] =
                make_float2(acc[mt][nt][2], acc[mt][nt][3]);
        }
}

// ---------------------------------------------------------------------------
// Kernel 1b+2: packed j-permuted fp16 tiles + sl/sr tables (round-8 exact).
// ---------------------------------------------------------------------------
__global__ __launch_bounds__(256) void k_whT2s(const float* __restrict__ al,
                                               const float* __restrict__ ar) {
    __shared__ float T[128][33];
    int jc = blockIdx.x, h = blockIdx.y;
    int tid = threadIdx.x;
    int warp = tid >> 5, lane = tid & 31;
    int j0 = jc * 32;

#pragma unroll
    for (int q = 0; q < 4; q++) {
        int f = tid + 256 * q;
        int j = f >> 5;
        int dq = (f & 31) * 4;
        float4 v = *(const float4*)(g_Wh + (size_t)(j0 + j) * ODIM + h * DK + dq);
        T[dq + 0][j] = v.x;
        T[dq + 1][j] = v.y;
        T[dq + 2][j] = v.z;
        T[dq + 3][j] = v.w;
    }
    __syncthreads();

    __half* tile = g_WhT2 + (size_t)(h * NCHUNK + jc) * TILE_H;
#pragma unroll
    for (int q = 0; q < 8; q++) {
        int f = tid + 256 * q;
        int row = f >> 4;
        int jp = f & 15;
        int blk = jp >> 3;
        int qq = jp & 7;
        int slot = ((qq & 3) * 2 + (qq >> 2));
        __half2 hv = __floats2half2_rn(T[row][2 * jp], T[row][2 * jp + 1]);
        *(__half2*)&tile[row * 32 + blk * 16 + slot * 2] = hv;
    }

#pragma unroll
    for (int rr = 0; rr < 4; rr++) {
        int j = warp * 4 + rr;
        float s1 = 0.f, s2 = 0.f;
#pragma unroll
        for (int q = 0; q < 4; q++) {
            int d = lane + 32 * q;
            float v = T[d][j];
            s1 = fmaf(v, al[h * DK + d], s1);
            s2 = fmaf(v, ar[h * DK + d], s2);
        }
#pragma unroll
        for (int o = 16; o > 0; o >>= 1) {
            s1 += __shfl_down_sync(0xffffffffu, s1, o);
            s2 += __shfl_down_sync(0xffffffffu, s2, o);
        }
        if (lane == 0) {
            int i = j0 + j;
            g_El2[h * NN + i] = make_float2(__expf(s1), __expf(SLOPE * s1));
            g_Er2[h * NN + i] = make_float2(__expf(s2), __expf(SLOPE * s2));
        }
    }
}

// ---------------------------------------------------------------------------
// Kernel 3: split-K aggregation (round-11 tile/alpha/layouts exactly).
// ONLY change: 3-stage cp.async pipeline, wait_group 1 in steady state ->
// two chunks in flight, two chunk-times of load latency budget.
// ---------------------------------------------------------------------------
__global__ __launch_bounds__(256, 2) void k_agg_p() {
    extern __shared__ __align__(16) char asm_[];

    int tid = threadIdx.x;
    int warp = tid >> 5, lane = tid & 31;
    int g = lane >> 2, tg = lane & 3;
    int h = blockIdx.y;
    int i0 = blockIdx.x * 128;
    int half = blockIdx.z;
    int cb = half * (NCHUNK / 2);
    const int NC = NCHUNK / 2;

    float el1[2], el2[2];
#pragma unroll
    for (int s = 0; s < 2; s++) {
        int r = i0 + 16 * warp + 8 * s + g;
        float2 e = g_El2[(size_t)h * NN + r];
        el1[s] = e.x * WSCALE;
        el2[s] = e.y * WSCALE;
    }

    auto tilep = [&](int s) -> __half* { return (__half*)(asm_ + s * AG_STAGE_B); };
    auto ersp  = [&](int s) -> float4* { return (float4*)(asm_ + s * AG_STAGE_B + AG_ERS_OFF); };
    auto amsp  = [&](int s) -> unsigned* { return (unsigned*)(asm_ + s * AG_STAGE_B + AG_AMS_OFF); };

    auto issue = [&](int cc, int s) {
        const __half* tp = g_WhT2 + (size_t)(h * NCHUNK + cc) * TILE_H;
        __half* dst = tilep(s);
#pragma unroll
        for (int q = 0; q < 2; q++) {
            int f = tid + 256 * q;
            int row = f >> 2, seg = (f & 3) * 8;
            cp16(&dst[row * SROW + seg], tp + row * 32 + seg);
        }
        if (tid < 16) cp16(&ersp(s)[tid], g_Er2 + (size_t)h * NN + cc * 32 + 2 * tid);
        if (tid < 32) cp16(&amsp(s)[tid * 4], g_Am + (size_t)cc * NN + i0 + tid * 4);
        asm volatile("cp.async.commit_group;");
    };

    float acc[16][4];
#pragma unroll
    for (int nt = 0; nt < 16; nt++)
#pragma unroll
        for (int q = 0; q < 4; q++) acc[nt][q] = 0.f;
    float zac[2] = {0.f, 0.f};

    issue(cb + 0, 0);
    issue(cb + 1, 1);

    for (int c = 0; c < NC; c++) {
        int s = c % 3;
        if (c + 1 < NC) {
            asm volatile("cp.async.wait_group 1;");   // chunk c done, c+1 streaming
        } else {
            asm volatile("cp.async.wait_group 0;");   // last chunk: need it complete
        }
        __syncthreads();
        if (c + 2 < NC) issue(cb + c + 2, (c + 2) % 3);

        const __half* Whs = tilep(s);
        const float4* Ers4 = ersp(s);
        const unsigned* Ams = amsp(s);

        unsigned mw0 = Ams[16 * warp + g];
        unsigned mw1 = Ams[16 * warp + 8 + g];

        unsigned aF[2][4];
#pragma unroll
        for (int kt = 0; kt < 2; kt++) {
            float4 eA = Ers4[8 * kt + tg];
            float4 eB = Ers4[8 * kt + tg + 4];
            int jb = 16 * kt + 2 * tg;
            {
                float w0 = fmaxf(el1[0] * eA.x, el2[0] * eA.y);
                if (!((mw0 >> jb) & 1u)) w0 = 0.f;
                float w1 = fmaxf(el1[0] * eA.z, el2[0] * eA.w);
                if (!((mw0 >> (jb + 1)) & 1u)) w1 = 0.f;
                float w8 = fmaxf(el1[0] * eB.x, el2[0] * eB.y);
                if (!((mw0 >> (jb + 8)) & 1u)) w8 = 0.f;
                float w9 = fmaxf(el1[0] * eB.z, el2[0] * eB.w);
                if (!((mw0 >> (jb + 9)) & 1u)) w9 = 0.f;
                zac[0] += (w0 + w1) + (w8 + w9);
                aF[kt][0] = packh2(w0, w1);
                aF[kt][2] = packh2(w8, w9);
            }
            {
                float w0 = fmaxf(el1[1] * eA.x, el2[1] * eA.y);
                if (!((mw1 >> jb) & 1u)) w0 = 0.f;
                float w1 = fmaxf(el1[1] * eA.z, el2[1] * eA.w);
                if (!((mw1 >> (jb + 1)) & 1u)) w1 = 0.f;
                float w8 = fmaxf(el1[1] * eB.x, el2[1] * eB.y);
                if (!((mw1 >> (jb + 8)) & 1u)) w8 = 0.f;
                float w9 = fmaxf(el1[1] * eB.z, el2[1] * eB.w);
                if (!((mw1 >> (jb + 9)) & 1u)) w9 = 0.f;
                zac[1] += (w0 + w1) + (w8 + w9);
                aF[kt][1] = packh2(w0, w1);
                aF[kt][3] = packh2(w8, w9);
            }
        }

#pragma unroll
        for (int kt = 0; kt < 2; kt++) {
#pragma unroll
            for (int nt = 0; nt < 16; nt++) {
                int drow = 8 * nt + g;
                uint2 bb = *(const uint2*)&Whs[drow * SROW + 16 * kt + 4 * tg];
                mma_f16(acc[nt], aF[kt][0], aF[kt][1], aF[kt][2], aF[kt][3], bb.x, bb.y);
            }
        }
    }

    // partial Z per row (quad-reduce)
    float z0 = zac[0], z1 = zac[1];
    z0 += __shfl_xor_sync(0xffffffffu, z0, 1);
    z0 += __shfl_xor_sync(0xffffffffu, z0, 2);
    z1 += __shfl_xor_sync(0xffffffffu, z1, 1);
    z1 += __shfl_xor_sync(0xffffffffu, z1, 2);
    float* zp = half ? g_zp1 : g_zp0;
    if (tg == 0) {
        zp[(size_t)h * NN + i0 + 16 * warp + g] = z0;
        zp[(size_t)h * NN + i0 + 16 * warp + 8 + g] = z1;
    }

    // partial sums to gmem (raw, scaled)
    float* pp = half ? g_part1 : g_part0;
#pragma unroll
    for (int nt = 0; nt < 16; nt++) {
        int col = h * DK + 8 * nt + 2 * tg;
        int row0 = i0 + 16 * warp + g;
        *(float2*)(pp + (size_t)row0 * ODIM + col) = make_float2(acc[nt][0], acc[nt][1]);
        *(float2*)(pp + (size_t)(row0 + 8) * ODIM + col) = make_float2(acc[nt][2], acc[nt][3]);
    }
}

// ---------------------------------------------------------------------------
// Kernel 4: combine halves, normalize, ELU (round-11 exact).
// ---------------------------------------------------------------------------
__global__ __launch_bounds__(256) void k_comb(float* __restrict__ out) {
    int t = blockIdx.x * 256 + threadIdx.x;
    int row = t >> 7;
    int col4 = t & 127;
    int h = col4 >> 5;
    float z = g_zp0[(size_t)h * NN + row] + g_zp1[(size_t)h * NN + row];
    float invz = __fdividef(1.f, z);
    float4 p0 = ((const float4*)g_part0)[t];
    float4 p1 = ((const float4*)g_part1)[t];
    float4 v;
    v.x = (p0.x + p1.x) * invz;
    v.y = (p0.y + p1.y) * invz;
    v.z = (p0.z + p1.z) * invz;
    v.w = (p0.w + p1.w) * invz;
    v.x = v.x > 0.f ? v.x : (__expf(v.x) - 1.f);
    v.y = v.y > 0.f ? v.y : (__expf(v.y) - 1.f);
    v.z = v.z > 0.f ? v.z : (__expf(v.z) - 1.f);
    v.w = v.w > 0.f ? v.w : (__expf(v.w) - 1.f);
    ((float4*)out)[t] = v;
}

// ---------------------------------------------------------------------------
extern "C" void kernel_launch(void* const* d_in, const int* in_sizes, int n_in,
                              void* d_out, int out_size) {
    const float* H  = (const float*)d_in[0];
    const int*   A  = (const int*)d_in[1];
    const float* W  = (const float*)d_in[2];
    const float* al = (const float*)d_in[3];
    const float* ar = (const float*)d_in[4];
    float* out = (float*)d_out;

    cudaFuncSetAttribute(k_gemm2, cudaFuncAttributeMaxDynamicSharedMemorySize,
                         G2_SMEM);
    cudaFuncSetAttribute(k_agg_p, cudaFuncAttributeMaxDynamicSharedMemorySize,
                         AG_SMEM);

    k_prep<<<2816, 256>>>(A, H, W);
    k_gemm2<<<dim3(ODIM / 64, NN / 128), 256, G2_SMEM>>>();
    k_whT2s<<<dim3(NCHUNK, NH), 256>>>(al, ar);
    k_agg_p<<<dim3(NN / 128, NH, 2), 256, AG_SMEM>>>();
    k_comb<<<(NN * ODIM / 4) / 256, 256>>>(out);
}

// round 15
// speedup vs baseline: 1.2132x; 1.0437x over previous
#include <cuda_runtime.h>
#include <cuda_fp16.h>
#include <math.h>
#include <stdint.h>

#define NN    4096
#define KDIM  512
#define ODIM  512
#define NH    4
#define DK    128
#define SLOPE 0.2f

#define NCHUNK     128            // NN / 32
#define TROW       40             // gemm2 fp16 smem row stride (halves)
#define TILE_H     (128 * 32)     // packed gmem tile: 128 d-rows x 32 j halves
#define SROW       80             // k_agg smem tile row stride (halves): 160B
#define WSCALE     0.0625f        // 2^-4, cancels in (p0+p1)/(z0+z1)

#define G2_STAGE_B 30720
#define G2_SMEM    (2 * G2_STAGE_B)

// ---------------- device scratch (no runtime allocation) ----------------
__device__ float  g_Wh[NN * ODIM];                 // 8 MB fp32 [j][c]
__device__ __half g_WhT2[NH * NCHUNK * TILE_H];    // fp16 tiles (j-permuted)
__device__ __half g_Hh[NN * KDIM];
__device__ __half g_Hl[NN * KDIM];
__device__ __half g_WTh[ODIM * KDIM];
__device__ __half g_WTl[ODIM * KDIM];
__device__ float2 g_El2[NH * NN];
__device__ float2 g_Er2[NH * NN];
__device__ unsigned g_Am[NCHUNK * NN];
__device__ float  g_part0[NN * ODIM];
__device__ float  g_part1[NN * ODIM];
__device__ float  g_zp0[NH * NN];
__device__ float  g_zp1[NH * NN];

// ---------------- helpers ----------------
__device__ __forceinline__ void mma_f16(float* c, unsigned a0, unsigned a1,
                                        unsigned a2, unsigned a3,
                                        unsigned b0, unsigned b1) {
    asm("mma.sync.aligned.m16n8k16.row.col.f32.f16.f16.f32 "
        "{%0,%1,%2,%3}, {%4,%5,%6,%7}, {%8,%9}, {%0,%1,%2,%3};"
        : "+f"(c[0]), "+f"(c[1]), "+f"(c[2]), "+f"(c[3])
        : "r"(a0), "r"(a1), "r"(a2), "r"(a3), "r"(b0), "r"(b1));
}
__device__ __forceinline__ unsigned packh2(float lo, float hi) {
    __half2 p = __floats2half2_rn(lo, hi);
    return *(unsigned*)&p;
}
__device__ __forceinline__ void cp16(void* smem_dst, const void* gsrc) {
    unsigned s = (unsigned)__cvta_generic_to_shared(smem_dst);
    asm volatile("cp.async.ca.shared.global [%0], [%1], 16;" :: "r"(s), "l"(gsrc));
}

// ---------------------------------------------------------------------------
// Prep kernel: splits ONLY (bitmask moved into the gemm2 union launch).
//   [0,2048): split H into fp16 hi/lo    [2048,2304): transpose+split W^T
// ---------------------------------------------------------------------------
__global__ __launch_bounds__(256) void k_prep(const float* __restrict__ H,
                                              const float* __restrict__ W) {
    __shared__ float T[32][33];
    int b = blockIdx.x;
    int tid = threadIdx.x;

    if (b < 2048) {
        int i4 = b * 256 + tid;
        float4 v = ((const float4*)H)[i4];
        __half hx = __float2half_rn(v.x), hy = __float2half_rn(v.y);
        __half hz = __float2half_rn(v.z), hw = __float2half_rn(v.w);
        __half2* ph = (__half2*)g_Hh;
        __half2* pl = (__half2*)g_Hl;
        ph[i4 * 2 + 0] = __halves2half2(hx, hy);
        ph[i4 * 2 + 1] = __halves2half2(hz, hw);
        pl[i4 * 2 + 0] = __floats2half2_rn(v.x - __half2float(hx), v.y - __half2float(hy));
        pl[i4 * 2 + 1] = __floats2half2_rn(v.z - __half2float(hz), v.w - __half2float(hw));
    } else {
        int idx = b - 2048;
        int kb = (idx & 15) * 32, nb = (idx >> 4) * 32;
        int x = tid & 31, y = tid >> 5;
#pragma unroll
        for (int q = 0; q < 32; q += 8)
            T[y + q][x] = W[(size_t)(kb + y + q) * ODIM + nb + x];
        __syncthreads();
#pragma unroll
        for (int q = 0; q < 32; q += 8) {
            float v = T[x][y + q];
            __half hi = __float2half_rn(v);
            size_t o = (size_t)(nb + y + q) * KDIM + kb + x;
            g_WTh[o] = hi;
            g_WTl[o] = __float2half_rn(v - __half2float(hi));
        }
    }
}

// ---------------------------------------------------------------------------
// Kernel 1 (union): blocks [0,256) = split-fp16 GEMM (round-8 exact code);
// blocks [256,768) = adjacency bitmask (DRAM-bound, overlaps the GEMM).
// ---------------------------------------------------------------------------
__global__ __launch_bounds__(256) void k_gemm2u(const int* __restrict__ A) {
    extern __shared__ __align__(16) char dsm[];

    int bb = blockIdx.x;
    int tid = threadIdx.x;
    int warp = tid >> 5, lane = tid & 31;

    if (bb >= 256) {
        // ---- adjacency bitmask: 8 rows per block, one warp per row ----
        int i = (bb - 256) * 8 + warp;
        const int* Arow = A + (size_t)i * NN;
        int dc = i >> 5;
        unsigned dbit = 1u << (i & 31);
        for (int c = 0; c < NCHUNK; c++) {
            int v = Arow[c * 32 + lane];
            unsigned bal = __ballot_sync(0xffffffffu, v > 0);
            if (c == dc) bal |= dbit;
            if (lane == 0) g_Am[(size_t)c * NN + i] = bal;
        }
        return;
    }

    // ---- GEMM part ----
    int g = lane >> 2, tg = lane & 3;
    int wm = warp & 3, wn = warp >> 2;
    int m0 = (bb >> 3) * 128, n0 = (bb & 7) * 64;

    auto issue = [&](int ks, int s) {
        char* base = dsm + s * G2_STAGE_B;
        __half* Ah_ = (__half*)base;
        __half* Al_ = (__half*)(base + 10240);
        __half* Bh_ = (__half*)(base + 20480);
        __half* Bl_ = (__half*)(base + 25600);
        int k0 = ks * 32;
#pragma unroll
        for (int q = 0; q < 2; q++) {
            int f = tid + 256 * q;
            int r = f >> 2, seg = (f & 3) * 8;
            cp16(&Ah_[r * TROW + seg], &g_Hh[(size_t)(m0 + r) * KDIM + k0 + seg]);
            cp16(&Al_[r * TROW + seg], &g_Hl[(size_t)(m0 + r) * KDIM + k0 + seg]);
        }
        {
            int r = tid >> 2, seg = (tid & 3) * 8;
            cp16(&Bh_[r * TROW + seg], &g_WTh[(size_t)(n0 + r) * KDIM + k0 + seg]);
            cp16(&Bl_[r * TROW + seg], &g_WTl[(size_t)(n0 + r) * KDIM + k0 + seg]);
        }
        asm volatile("cp.async.commit_group;");
    };

    float acc[2][4][4];
#pragma unroll
    for (int mt = 0; mt < 2; mt++)
#pragma unroll
        for (int nt = 0; nt < 4; nt++)
#pragma unroll
            for (int q = 0; q < 4; q++) acc[mt][nt][q] = 0.f;

    issue(0, 0);

    for (int ks = 0; ks < KDIM / 32; ks++) {
        int s = ks & 1;
        if (ks + 1 < KDIM / 32) {
            issue(ks + 1, s ^ 1);
            asm volatile("cp.async.wait_group 1;");
        } else {
            asm volatile("cp.async.wait_group 0;");
        }
        __syncthreads();

        const char* base = dsm + s * G2_STAGE_B;
        const __half* Ah_ = (const __half*)base;
        const __half* Al_ = (const __half*)(base + 10240);
        const __half* Bh_ = (const __half*)(base + 20480);
        const __half* Bl_ = (const __half*)(base + 25600);

#pragma unroll
        for (int kt = 0; kt < 2; kt++) {
            int kb = 16 * kt + 2 * tg;
            unsigned ah[2][4], al_[2][4];
#pragma unroll
            for (int mt = 0; mt < 2; mt++) {
                int rb = 32 * wm + 16 * mt + g;
                ah[mt][0] = *(const unsigned*)&Ah_[rb * TROW + kb];
                ah[mt][1] = *(const unsigned*)&Ah_[(rb + 8) * TROW + kb];
                ah[mt][2] = *(const unsigned*)&Ah_[rb * TROW + kb + 8];
                ah[mt][3] = *(const unsigned*)&Ah_[(rb + 8) * TROW + kb + 8];
                al_[mt][0] = *(const unsigned*)&Al_[rb * TROW + kb];
                al_[mt][1] = *(const unsigned*)&Al_[(rb + 8) * TROW + kb];
                al_[mt][2] = *(const unsigned*)&Al_[rb * TROW + kb + 8];
                al_[mt][3] = *(const unsigned*)&Al_[(rb + 8) * TROW + kb + 8];
            }
#pragma unroll
            for (int nt = 0; nt < 4; nt++) {
                int nl = 32 * wn + 8 * nt + g;
                unsigned bh0 = *(const unsigned*)&Bh_[nl * TROW + kb];
                unsigned bh1 = *(const unsigned*)&Bh_[nl * TROW + kb + 8];
                unsigned bl0 = *(const unsigned*)&Bl_[nl * TROW + kb];
                unsigned bl1 = *(const unsigned*)&Bl_[nl * TROW + kb + 8];
#pragma unroll
                for (int mt = 0; mt < 2; mt++) {
                    mma_f16(acc[mt][nt], ah[mt][0], ah[mt][1], ah[mt][2], ah[mt][3], bh0, bh1);
                    mma_f16(acc[mt][nt], ah[mt][0], ah[mt][1], ah[mt][2], ah[mt][3], bl0, bl1);
                    mma_f16(acc[mt][nt], al_[mt][0], al_[mt][1], al_[mt][2], al_[mt][3], bh0, bh1);
                }
            }
        }
        __syncthreads();
    }

#pragma unroll
    for (int mt = 0; mt < 2; mt++)
#pragma unroll
        for (int nt = 0; nt < 4; nt++) {
            int row = m0 + 32 * wm + 16 * mt + g;
            int col = n0 + 32 * wn + 8 * nt + 2 * tg;
            *(float2*)&g_Wh[(size_t)row * ODIM + col] =
                make_float2(acc[mt][nt][0], acc[mt][nt][1]);
            *(float2*)&g_Wh[(size_t)(row + 8) * ODIM + col] =
                make_float2(acc[mt][nt][2], acc[mt][nt][3]);
        }
}

// ---------------------------------------------------------------------------
// Kernel 1b+2: packed j-permuted fp16 tiles + sl/sr tables (round-8 exact).
// ---------------------------------------------------------------------------
__global__ __launch_bounds__(256) void k_whT2s(const float* __restrict__ al,
                                               const float* __restrict__ ar) {
    __shared__ float T[128][33];
    int jc = blockIdx.x, h = blockIdx.y;
    int tid = threadIdx.x;
    int warp = tid >> 5, lane = tid & 31;
    int j0 = jc * 32;

#pragma unroll
    for (int q = 0; q < 4; q++) {
        int f = tid + 256 * q;
        int j = f >> 5;
        int dq = (f & 31) * 4;
        float4 v = *(const float4*)(g_Wh + (size_t)(j0 + j) * ODIM + h * DK + dq);
        T[dq + 0][j] = v.x;
        T[dq + 1][j] = v.y;
        T[dq + 2][j] = v.z;
        T[dq + 3][j] = v.w;
    }
    __syncthreads();

    __half* tile = g_WhT2 + (size_t)(h * NCHUNK + jc) * TILE_H;
#pragma unroll
    for (int q = 0; q < 8; q++) {
        int f = tid + 256 * q;
        int row = f >> 4;
        int jp = f & 15;
        int blk = jp >> 3;
        int qq = jp & 7;
        int slot = ((qq & 3) * 2 + (qq >> 2));
        __half2 hv = __floats2half2_rn(T[row][2 * jp], T[row][2 * jp + 1]);
        *(__half2*)&tile[row * 32 + blk * 16 + slot * 2] = hv;
    }

#pragma unroll
    for (int rr = 0; rr < 4; rr++) {
        int j = warp * 4 + rr;
        float s1 = 0.f, s2 = 0.f;
#pragma unroll
        for (int q = 0; q < 4; q++) {
            int d = lane + 32 * q;
            float v = T[d][j];
            s1 = fmaf(v, al[h * DK + d], s1);
            s2 = fmaf(v, ar[h * DK + d], s2);
        }
#pragma unroll
        for (int o = 16; o > 0; o >>= 1) {
            s1 += __shfl_down_sync(0xffffffffu, s1, o);
            s2 += __shfl_down_sync(0xffffffffu, s2, o);
        }
        if (lane == 0) {
            int i = j0 + j;
            g_El2[h * NN + i] = make_float2(__expf(s1), __expf(SLOPE * s1));
            g_Er2[h * NN + i] = make_float2(__expf(s2), __expf(SLOPE * s2));
        }
    }
}

// ---------------------------------------------------------------------------
// Kernel 3: split-K aggregation (round-11 exact: 16i x 128d warp tile,
// alpha once, single barrier per chunk, 2-stage cp.async).
// ---------------------------------------------------------------------------
__global__ __launch_bounds__(256, 2) void k_agg_p() {
    __shared__ __half Whs[2][128 * SROW];
    __shared__ float4 Ers4[2][16];
    __shared__ unsigned Ams[2][128];

    int tid = threadIdx.x;
    int warp = tid >> 5, lane = tid & 31;
    int g = lane >> 2, tg = lane & 3;
    int h = blockIdx.y;
    int i0 = blockIdx.x * 128;
    int half = blockIdx.z;
    int cb = half * (NCHUNK / 2);

    float el1[2], el2[2];
#pragma unroll
    for (int s = 0; s < 2; s++) {
        int r = i0 + 16 * warp + 8 * s + g;
        float2 e = g_El2[(size_t)h * NN + r];
        el1[s] = e.x * WSCALE;
        el2[s] = e.y * WSCALE;
    }

    auto issue = [&](int cc, int s) {
        const __half* tp = g_WhT2 + (size_t)(h * NCHUNK + cc) * TILE_H;
#pragma unroll
        for (int q = 0; q < 2; q++) {
            int f = tid + 256 * q;
            int row = f >> 2, seg = (f & 3) * 8;
            cp16(&Whs[s][row * SROW + seg], tp + row * 32 + seg);
        }
        if (tid < 16) cp16(&Ers4[s][tid], g_Er2 + (size_t)h * NN + cc * 32 + 2 * tid);
        if (tid < 32) cp16(&Ams[s][tid * 4], g_Am + (size_t)cc * NN + i0 + tid * 4);
        asm volatile("cp.async.commit_group;");
    };

    float acc[16][4];
#pragma unroll
    for (int nt = 0; nt < 16; nt++)
#pragma unroll
        for (int q = 0; q < 4; q++) acc[nt][q] = 0.f;
    float zac[2] = {0.f, 0.f};

    issue(cb, 0);

    for (int c = 0; c < NCHUNK / 2; c++) {
        int s = c & 1;
        asm volatile("cp.async.wait_group 0;");
        __syncthreads();
        if (c + 1 < NCHUNK / 2) issue(cb + c + 1, s ^ 1);

        unsigned mw0 = Ams[s][16 * warp + g];
        unsigned mw1 = Ams[s][16 * warp + 8 + g];

        unsigned aF[2][4];
#pragma unroll
        for (int kt = 0; kt < 2; kt++) {
            float4 eA = Ers4[s][8 * kt + tg];
            float4 eB = Ers4[s][8 * kt + tg + 4];
            int jb = 16 * kt + 2 * tg;
            {
                float w0 = fmaxf(el1[0] * eA.x, el2[0] * eA.y);
                if (!((mw0 >> jb) & 1u)) w0 = 0.f;
                float w1 = fmaxf(el1[0] * eA.z, el2[0] * eA.w);
                if (!((mw0 >> (jb + 1)) & 1u)) w1 = 0.f;
                float w8 = fmaxf(el1[0] * eB.x, el2[0] * eB.y);
                if (!((mw0 >> (jb + 8)) & 1u)) w8 = 0.f;
                float w9 = fmaxf(el1[0] * eB.z, el2[0] * eB.w);
                if (!((mw0 >> (jb + 9)) & 1u)) w9 = 0.f;
                zac[0] += (w0 + w1) + (w8 + w9);
                aF[kt][0] = packh2(w0, w1);
                aF[kt][2] = packh2(w8, w9);
            }
            {
                float w0 = fmaxf(el1[1] * eA.x, el2[1] * eA.y);
                if (!((mw1 >> jb) & 1u)) w0 = 0.f;
                float w1 = fmaxf(el1[1] * eA.z, el2[1] * eA.w);
                if (!((mw1 >> (jb + 1)) & 1u)) w1 = 0.f;
                float w8 = fmaxf(el1[1] * eB.x, el2[1] * eB.y);
                if (!((mw1 >> (jb + 8)) & 1u)) w8 = 0.f;
                float w9 = fmaxf(el1[1] * eB.z, el2[1] * eB.w);
                if (!((mw1 >> (jb + 9)) & 1u)) w9 = 0.f;
                zac[1] += (w0 + w1) + (w8 + w9);
                aF[kt][1] = packh2(w0, w1);
                aF[kt][3] = packh2(w8, w9);
            }
        }

#pragma unroll
        for (int kt = 0; kt < 2; kt++) {
#pragma unroll
            for (int nt = 0; nt < 16; nt++) {
                int drow = 8 * nt + g;
                uint2 bb = *(const uint2*)&Whs[s][drow * SROW + 16 * kt + 4 * tg];
                mma_f16(acc[nt], aF[kt][0], aF[kt][1], aF[kt][2], aF[kt][3], bb.x, bb.y);
            }
        }
    }

    // partial Z per row (quad-reduce)
    float z0 = zac[0], z1 = zac[1];
    z0 += __shfl_xor_sync(0xffffffffu, z0, 1);
    z0 += __shfl_xor_sync(0xffffffffu, z0, 2);
    z1 += __shfl_xor_sync(0xffffffffu, z1, 1);
    z1 += __shfl_xor_sync(0xffffffffu, z1, 2);
    float* zp = half ? g_zp1 : g_zp0;
    if (tg == 0) {
        zp[(size_t)h * NN + i0 + 16 * warp + g] = z0;
        zp[(size_t)h * NN + i0 + 16 * warp + 8 + g] = z1;
    }

    // partial sums to gmem (raw, scaled)
    float* pp = half ? g_part1 : g_part0;
#pragma unroll
    for (int nt = 0; nt < 16; nt++) {
        int col = h * DK + 8 * nt + 2 * tg;
        int row0 = i0 + 16 * warp + g;
        *(float2*)(pp + (size_t)row0 * ODIM + col) = make_float2(acc[nt][0], acc[nt][1]);
        *(float2*)(pp + (size_t)(row0 + 8) * ODIM + col) = make_float2(acc[nt][2], acc[nt][3]);
    }
}

// ---------------------------------------------------------------------------
// Kernel 4: combine halves, normalize, ELU (round-11 exact).
// ---------------------------------------------------------------------------
__global__ __launch_bounds__(256) void k_comb(float* __restrict__ out) {
    int t = blockIdx.x * 256 + threadIdx.x;
    int row = t >> 7;
    int col4 = t & 127;
    int h = col4 >> 5;
    float z = g_zp0[(size_t)h * NN + row] + g_zp1[(size_t)h * NN + row];
    float invz = __fdividef(1.f, z);
    float4 p0 = ((const float4*)g_part0)[t];
    float4 p1 = ((const float4*)g_part1)[t];
    float4 v;
    v.x = (p0.x + p1.x) * invz;
    v.y = (p0.y + p1.y) * invz;
    v.z = (p0.z + p1.z) * invz;
    v.w = (p0.w + p1.w) * invz;
    v.x = v.x > 0.f ? v.x : (__expf(v.x) - 1.f);
    v.y = v.y > 0.f ? v.y : (__expf(v.y) - 1.f);
    v.z = v.z > 0.f ? v.z : (__expf(v.z) - 1.f);
    v.w = v.w > 0.f ? v.w : (__expf(v.w) - 1.f);
    ((float4*)out)[t] = v;
}

// ---------------------------------------------------------------------------
extern "C" void kernel_launch(void* const* d_in, const int* in_sizes, int n_in,
                              void* d_out, int out_size) {
    const float* H  = (const float*)d_in[0];
    const int*   A  = (const int*)d_in[1];
    const float* W  = (const float*)d_in[2];
    const float* al = (const float*)d_in[3];
    const float* ar = (const float*)d_in[4];
    float* out = (float*)d_out;

    cudaFuncSetAttribute(k_gemm2u, cudaFuncAttributeMaxDynamicSharedMemorySize,
                         G2_SMEM);

    k_prep<<<2304, 256>>>(H, W);
    k_gemm2u<<<768, 256, G2_SMEM>>>(A);
    k_whT2s<<<dim3(NCHUNK, NH), 256>>>(al, ar);
    k_agg_p<<<dim3(NN / 128, NH, 2), 256>>>();
    k_comb<<<(NN * ODIM / 4) / 256, 256>>>(out);
}